// round 1
// baseline (speedup 1.0000x reference)
#include <cuda_runtime.h>
#include <math.h>

#define B_ 2
#define T_ 512
#define C_ 263
#define D_ 512
#define F_ 257          // T/2 + 1
#define K_TOP 51        // int(512 * 0.1)
#define WIN_ 24

// ---------------- scratch (static device memory; no allocation) ----------------
__device__ float g_ex [B_*T_*D_];
__device__ float g_h  [B_*T_*D_];
__device__ float g_mtd[B_*T_*D_];
__device__ float2 g_cx[B_*F_*D_];       // (re, im), layout [b][f][d]
__device__ float g_mx [B_*T_*C_];
__device__ float g_score[B_*T_];
__device__ float g_mag  [B_*F_];
__device__ int   g_tidx[B_*K_TOP];
__device__ int   g_fidx[B_*K_TOP];
__device__ unsigned char g_tmask[B_*T_];
__device__ unsigned char g_fmask[B_*F_];
__device__ unsigned char g_tm   [B_*T_];
__device__ float g_costab[512];
__device__ float g_sintab[512];
__device__ float g_pe[T_*D_];

// ---------------- table init (cheap, re-run every launch for determinism) ------
__global__ void init_tables_kernel() {
    int i = blockIdx.x * blockDim.x + threadIdx.x;
    if (i < 512) {
        float s, c;
        sincospif((float)i / 256.0f, &s, &c);   // 2*pi*i/512
        g_costab[i] = c; g_sintab[i] = s;
    }
    if (i < T_ * D_) {
        int t = i / D_, d = i % D_;
        // matches numpy: double-precision exp/sin/cos, stored as fp32
        double div = exp(-(double)(d & ~1) * (9.210340371976184 / 512.0));
        double arg = (double)t * div;
        g_pe[i] = (float)((d & 1) ? cos(arg) : sin(arg));
    }
}

// ---------------- generic tiled SGEMM: C[M,N] = A[M,K] * B(^T), epilogues ------
#define BM 64
#define BN 64
#define BK 16
#define EPI_NONE    0
#define EPI_PE      2
#define EPI_GELU    3
#define EPI_SIGMASK 4

__global__ void sgemm_kernel(const float* __restrict__ A, const float* __restrict__ B,
                             float* __restrict__ Cm,
                             int M, int N, int K, int bKN,
                             const float* __restrict__ bias, int epi,
                             const unsigned char* __restrict__ mask,
                             const float* __restrict__ token)
{
    __shared__ float As[BK][BM];
    __shared__ float Bs[BK][BN];
    int tid = threadIdx.x;            // 256 threads
    int bm = blockIdx.y * BM;
    int bn = blockIdx.x * BN;
    int tx = tid & 15, ty = tid >> 4;
    float acc[4][4] = {};

    for (int k0 = 0; k0 < K; k0 += BK) {
        {   // A tile: 64 rows x 16 k, 4 consecutive k per thread
            int m = tid >> 2;
            int kk0 = (tid & 3) * 4;
            int row = bm + m;
            #pragma unroll
            for (int j = 0; j < 4; j++) {
                int kk = kk0 + j;
                float v = 0.f;
                if (row < M && (k0 + kk) < K) v = A[row * K + k0 + kk];
                As[kk][m] = v;
            }
        }
        if (bKN) {  // B stored [K,N] (ld=N)
            int kk = tid >> 4;
            int n0 = (tid & 15) * 4;
            #pragma unroll
            for (int j = 0; j < 4; j++) {
                int n = n0 + j;
                float v = 0.f;
                if ((k0 + kk) < K && (bn + n) < N) v = B[(k0 + kk) * N + bn + n];
                Bs[kk][n] = v;
            }
        } else {    // B stored [N,K] (ld=K) — computes A * B^T
            int n = tid >> 2;
            int kk0 = (tid & 3) * 4;
            #pragma unroll
            for (int j = 0; j < 4; j++) {
                int kk = kk0 + j;
                float v = 0.f;
                if ((bn + n) < N && (k0 + kk) < K) v = B[(bn + n) * K + k0 + kk];
                Bs[kk][n] = v;
            }
        }
        __syncthreads();
        #pragma unroll
        for (int kk = 0; kk < BK; kk++) {
            float a[4], b[4];
            #pragma unroll
            for (int i = 0; i < 4; i++) a[i] = As[kk][ty + 16 * i];
            #pragma unroll
            for (int j = 0; j < 4; j++) b[j] = Bs[kk][tx + 16 * j];
            #pragma unroll
            for (int i = 0; i < 4; i++)
                #pragma unroll
                for (int j = 0; j < 4; j++)
                    acc[i][j] = fmaf(a[i], b[j], acc[i][j]);
        }
        __syncthreads();
    }

    #pragma unroll
    for (int i = 0; i < 4; i++) {
        #pragma unroll
        for (int j = 0; j < 4; j++) {
            int row = bm + ty + 16 * i;
            int col = bn + tx + 16 * j;
            if (row < M && col < N) {
                float v = acc[i][j];
                if (epi == EPI_PE) {
                    v += bias[col];
                    int t = row & (T_ - 1);
                    v += g_pe[t * D_ + col];
                } else if (epi == EPI_GELU) {
                    v += bias[col];
                    v = 0.5f * v * (1.f + erff(v * 0.70710678118654752f));
                } else if (epi == EPI_SIGMASK) {
                    v += bias[col];
                    v = 1.f / (1.f + expf(-v));
                    if (mask[row]) v = token[col];
                }
                Cm[row * N + col] = v;
            }
        }
    }
}

// ---------------- windowed-variance score: one block per (b,t) -----------------
__global__ void score_kernel() {
    int bt = blockIdx.x;
    int b = bt >> 9, t = bt & 511;
    int tid = threadIdx.x;            // 256
    int t0 = t - (WIN_ - 1); if (t0 < 0) t0 = 0;
    float denom = (float)((t + 1 < WIN_) ? (t + 1) : WIN_);
    float num = 0.f, den = 0.f;
    for (int d = tid; d < D_; d += 256) {
        float s1 = 0.f, s2 = 0.f;
        const float* p = &g_ex[((size_t)b * T_ + t0) * D_ + d];
        for (int tt = t0; tt <= t; tt++) {
            float v = *p; p += D_;
            s1 += v;
            s2 = fmaf(v, v, s2);
        }
        float m1 = s1 / denom;
        num += s2 / denom - m1 * m1;
        den += m1;
    }
    __shared__ float sn[256], sd[256];
    sn[tid] = num; sd[tid] = den; __syncthreads();
    for (int s = 128; s > 0; s >>= 1) {
        if (tid < s) { sn[tid] += sn[tid + s]; sd[tid] += sd[tid + s]; }
        __syncthreads();
    }
    if (tid == 0) g_score[bt] = sn[0] / (sd[0] + 1e-6f);
}

// ---------------- top-k (lax.top_k semantics: value desc, index asc ties) ------
__global__ void topk_kernel(const float* __restrict__ vals, int n, int k,
                            int* __restrict__ idx_out,
                            unsigned char* __restrict__ mask_out,
                            float* __restrict__ outf)
{
    int b = blockIdx.x;
    int tid = threadIdx.x;            // 256
    __shared__ float v[512];
    __shared__ float bv[256];
    __shared__ int   bi[256];
    for (int i = tid; i < n; i += 256) {
        v[i] = vals[b * n + i];
        mask_out[b * n + i] = 0;
    }
    __syncthreads();
    for (int it = 0; it < k; it++) {
        float best = -INFINITY; int besti = n;
        for (int i = tid; i < n; i += 256) {
            float x = v[i];
            if (x > best || (x == best && i < besti)) { best = x; besti = i; }
        }
        bv[tid] = best; bi[tid] = besti; __syncthreads();
        for (int s = 128; s > 0; s >>= 1) {
            if (tid < s) {
                float x2 = bv[tid + s]; int i2 = bi[tid + s];
                if (x2 > bv[tid] || (x2 == bv[tid] && i2 < bi[tid])) { bv[tid] = x2; bi[tid] = i2; }
            }
            __syncthreads();
        }
        if (tid == 0) {
            int bidx = bi[0];
            idx_out[b * k + it] = bidx;
            outf[b * k + it] = (float)bidx;
            mask_out[b * n + bidx] = 1;
            v[bidx] = -INFINITY;
        }
        __syncthreads();
    }
}

// ---------------- rfft via DFT (exact (f*t) mod 512 indexing) ------------------
__global__ void rfft_kernel() {
    int bf = blockIdx.x;
    int b = bf / F_, f = bf % F_;
    int d = threadIdx.x;              // 512
    __shared__ float ct[512], st[512];
    ct[d] = g_costab[d]; st[d] = g_sintab[d];
    __syncthreads();
    float cr = 0.f, ci = 0.f;
    const float* p = &g_ex[(size_t)b * T_ * D_ + d];
    #pragma unroll 8
    for (int t = 0; t < T_; t++) {
        float x = p[(size_t)t * D_];
        int idx = (f * t) & 511;
        cr = fmaf(x, ct[idx], cr);
        ci = fmaf(-x, st[idx], ci);
    }
    g_cx[((size_t)b * F_ + f) * D_ + d] = make_float2(cr, ci);
    float mag = sqrtf(cr * cr + ci * ci);
    __shared__ float red[512];
    red[d] = mag; __syncthreads();
    for (int s = 256; s > 0; s >>= 1) {
        if (d < s) red[d] += red[d + s];
        __syncthreads();
    }
    if (d == 0) g_mag[b * F_ + f] = red[0] * (1.f / 512.f);
}

// ---------------- time-domain mask tm = irfft(fmask) != 0 ----------------------
__global__ void tm_kernel() {
    int b = blockIdx.x;
    int t = threadIdx.x;              // 512
    const unsigned char* fm = &g_fmask[b * F_];
    float y = fm[0] ? 1.f : 0.f;
    for (int f = 1; f < 256; f++)
        if (fm[f]) y += 2.f * g_costab[(f * t) & 511];
    if (fm[256]) y += (t & 1) ? -1.f : 1.f;
    g_tm[b * T_ + t] = (y != 0.f) ? 1 : 0;
}

// ---------------- masked irfft (imag of DC/Nyquist ignored, per C2R) -----------
__global__ void irfft_kernel(const float* __restrict__ f_tok_re,
                             const float* __restrict__ f_tok_im) {
    int bt = blockIdx.x;
    int b = bt >> 9, t = bt & 511;
    int d = threadIdx.x;              // 512
    __shared__ float ct[512], st[512];
    ct[d] = g_costab[d]; st[d] = g_sintab[d];
    __syncthreads();
    const unsigned char* fm = &g_fmask[b * F_];
    float tr = f_tok_re[d], ti = f_tok_im[d];
    const float2* cxb = &g_cx[(size_t)b * F_ * D_ + d];
    float acc = fm[0] ? tr : cxb[0].x;
    #pragma unroll 4
    for (int f = 1; f < 256; f++) {
        float re, im;
        if (fm[f]) { re = tr; im = ti; }
        else { float2 c = cxb[(size_t)f * D_]; re = c.x; im = c.y; }
        int idx = (f * t) & 511;
        acc += 2.f * (re * ct[idx] - im * st[idx]);
    }
    {
        float re = fm[256] ? tr : cxb[(size_t)256 * D_].x;
        acc += re * ((t & 1) ? -1.f : 1.f);
    }
    g_mtd[((size_t)b * T_ + t) * D_ + d] = acc * (1.f / 512.f);
}

// ---------------- out_f: mx where tm, else scalar MLP (usually dead) -----------
__global__ void outf_kernel(float* __restrict__ out,
                            const float* __restrict__ fW1, const float* __restrict__ fb1,
                            const float* __restrict__ fW2, const float* __restrict__ fb2)
{
    int i = blockIdx.x * blockDim.x + threadIdx.x;
    if (i >= B_ * T_ * C_) return;
    int bt = i / C_;
    float m = g_mx[i];
    if (g_tm[bt]) { out[i] = m; return; }
    float acc = 0.f;
    for (int dd = 0; dd < D_; dd++) {
        float u = fmaf(m, fW1[dd], fb1[dd]);
        float g = 0.5f * u * (1.f + erff(u * 0.70710678118654752f));
        acc = fmaf(g, fW2[dd], acc);
    }
    out[i] = 1.f / (1.f + expf(-(acc + fb2[0])));
}

// ---------------- launch ----------------
extern "C" void kernel_launch(void* const* d_in, const int* in_sizes, int n_in,
                              void* d_out, int out_size) {
    const float* x        = (const float*)d_in[0];
    const float* W_emb    = (const float*)d_in[1];
    const float* b_emb    = (const float*)d_in[2];
    const float* t_token  = (const float*)d_in[3];
    const float* tW1      = (const float*)d_in[4];
    const float* tb1      = (const float*)d_in[5];
    const float* tW2      = (const float*)d_in[6];
    const float* tb2      = (const float*)d_in[7];
    const float* f_tok_re = (const float*)d_in[8];
    const float* f_tok_im = (const float*)d_in[9];
    const float* fW1      = (const float*)d_in[10];
    const float* fb1      = (const float*)d_in[11];
    const float* fW2      = (const float*)d_in[12];
    const float* fb2      = (const float*)d_in[13];
    float* out = (float*)d_out;

    // output packing: out_t [B,T,D] | tidx [B,51] | out_f [B,T,C] | fidx [B,51]
    float* out_t    = out;
    float* out_tidx = out + (size_t)B_ * T_ * D_;
    float* out_f    = out_tidx + B_ * K_TOP;
    float* out_fidx = out_f + (size_t)B_ * T_ * C_;

    float *p_ex, *p_h, *p_mtd, *p_mx, *p_score, *p_mag;
    int *p_tidx, *p_fidx;
    unsigned char *p_tmask, *p_fmask;
    cudaGetSymbolAddress((void**)&p_ex,    g_ex);
    cudaGetSymbolAddress((void**)&p_h,     g_h);
    cudaGetSymbolAddress((void**)&p_mtd,   g_mtd);
    cudaGetSymbolAddress((void**)&p_mx,    g_mx);
    cudaGetSymbolAddress((void**)&p_score, g_score);
    cudaGetSymbolAddress((void**)&p_mag,   g_mag);
    cudaGetSymbolAddress((void**)&p_tidx,  g_tidx);
    cudaGetSymbolAddress((void**)&p_fidx,  g_fidx);
    cudaGetSymbolAddress((void**)&p_tmask, g_tmask);
    cudaGetSymbolAddress((void**)&p_fmask, g_fmask);

    init_tables_kernel<<<1024, 256>>>();

    // ex = x * W_emb^T + b_emb + PE     [1024,512] K=263
    sgemm_kernel<<<dim3(512 / BN, 1024 / BM), 256>>>(
        x, W_emb, p_ex, B_ * T_, D_, C_, 0, b_emb, EPI_PE, nullptr, nullptr);

    // temporal score + top-k
    score_kernel<<<B_ * T_, 256>>>();
    topk_kernel<<<B_, 256>>>(p_score, T_, K_TOP, p_tidx, p_tmask, out_tidx);

    // h = gelu(ex * tW1^T + tb1)
    sgemm_kernel<<<dim3(512 / BN, 1024 / BM), 256>>>(
        p_ex, tW1, p_h, B_ * T_, D_, D_, 0, tb1, EPI_GELU, nullptr, nullptr);

    // out_t = tmask ? t_token : sigmoid(h * tW2^T + tb2)
    sgemm_kernel<<<dim3(512 / BN, 1024 / BM), 256>>>(
        p_h, tW2, out_t, B_ * T_, D_, D_, 0, tb2, EPI_SIGMASK, p_tmask, t_token);

    // rfft + magnitude mean, freq top-k
    rfft_kernel<<<B_ * F_, 512>>>();
    topk_kernel<<<B_, 256>>>(p_mag, F_, K_TOP, p_fidx, p_fmask, out_fidx);

    // tm mask + masked irfft
    tm_kernel<<<B_, 512>>>();
    irfft_kernel<<<B_ * T_, 512>>>(f_tok_re, f_tok_im);

    // mx = mtd * W_emb  (B is [K=D, N=C], natural layout)
    sgemm_kernel<<<dim3((C_ + BN - 1) / BN, 1024 / BM), 256>>>(
        p_mtd, W_emb, p_mx, B_ * T_, C_, D_, 1, nullptr, EPI_NONE, nullptr, nullptr);

    // out_f
    outf_kernel<<<(B_ * T_ * C_ + 255) / 256, 256>>>(out_f, fW1, fb1, fW2, fb2);
}

// round 2
// speedup vs baseline: 1.3351x; 1.3351x over previous
#include <cuda_runtime.h>
#include <math.h>

#define B_ 2
#define T_ 512
#define C_ 263
#define D_ 512
#define F_ 257          // T/2 + 1
#define K_TOP 51        // int(512 * 0.1)
#define WIN_ 24

#define RF_G 4          // freqs per block in rfft
#define IR_G 8          // time points per block in irfft

// ---------------- scratch (static device memory; no allocation) ----------------
__device__ float g_ex [B_*T_*D_];
__device__ float g_h  [B_*T_*D_];
__device__ float g_mtd[B_*T_*D_];
__device__ float2 g_cx[B_*F_*D_];       // (re, im), layout [b][f][d]
__device__ float g_mx [B_*T_*C_];
__device__ float g_score[B_*T_];
__device__ float g_mag  [B_*F_];
__device__ int   g_tidx[B_*K_TOP];
__device__ int   g_fidx[B_*K_TOP];
__device__ unsigned char g_tmask[B_*T_];
__device__ unsigned char g_fmask[B_*F_];
__device__ unsigned char g_tm   [B_*T_];
__device__ float g_costab[512];
__device__ float g_sintab[512];
__device__ float g_pe[T_*D_];
__device__ double g_div[256];           // PE divisors (fp64)

// ---------------- table init ----------------------------------------------------
__global__ void init_div_kernel() {
    int i = threadIdx.x;                 // 512 threads
    if (i < 256) {
        // div for PE column pair i: exp(-(2i) * ln(10000)/512)
        g_div[i] = exp(-(double)(2 * i) * (9.210340371976184 / 512.0));
    }
    if (i < 512) {
        float s, c;
        sincospif((float)i / 256.0f, &s, &c);   // 2*pi*i/512
        g_costab[i] = c; g_sintab[i] = s;
    }
}

__global__ void init_pe_kernel() {
    int i = blockIdx.x * blockDim.x + threadIdx.x;
    if (i >= T_ * D_) return;
    int t = i / D_, d = i % D_;
    double arg = (double)t * g_div[d >> 1];
    // double-precision range reduction to [-pi, pi], then float sin/cos
    const double PI2   = 6.283185307179586476925286766559;
    double q = rint(arg * (1.0 / PI2));
    double r = arg - q * PI2;
    float rf = (float)r;
    g_pe[i] = (d & 1) ? cosf(rf) : sinf(rf);
}

// ---------------- generic tiled SGEMM: C[M,N] = A[M,K] * B(^T), epilogues ------
#define BM 64
#define BN 64
#define BK 16
#define EPI_NONE    0
#define EPI_PE      2
#define EPI_GELU    3
#define EPI_SIGMASK 4

__global__ void sgemm_kernel(const float* __restrict__ A, const float* __restrict__ B,
                             float* __restrict__ Cm,
                             int M, int N, int K, int bKN,
                             const float* __restrict__ bias, int epi,
                             const unsigned char* __restrict__ mask,
                             const float* __restrict__ token)
{
    __shared__ float As[BK][BM];
    __shared__ float Bs[BK][BN];
    int tid = threadIdx.x;            // 256 threads
    int bm = blockIdx.y * BM;
    int bn = blockIdx.x * BN;
    int tx = tid & 15, ty = tid >> 4;
    float acc[4][4] = {};

    for (int k0 = 0; k0 < K; k0 += BK) {
        {   // A tile: 64 rows x 16 k, 4 consecutive k per thread
            int m = tid >> 2;
            int kk0 = (tid & 3) * 4;
            int row = bm + m;
            #pragma unroll
            for (int j = 0; j < 4; j++) {
                int kk = kk0 + j;
                float v = 0.f;
                if (row < M && (k0 + kk) < K) v = A[row * K + k0 + kk];
                As[kk][m] = v;
            }
        }
        if (bKN) {  // B stored [K,N] (ld=N)
            int kk = tid >> 4;
            int n0 = (tid & 15) * 4;
            #pragma unroll
            for (int j = 0; j < 4; j++) {
                int n = n0 + j;
                float v = 0.f;
                if ((k0 + kk) < K && (bn + n) < N) v = B[(k0 + kk) * N + bn + n];
                Bs[kk][n] = v;
            }
        } else {    // B stored [N,K] (ld=K) — computes A * B^T
            int n = tid >> 2;
            int kk0 = (tid & 3) * 4;
            #pragma unroll
            for (int j = 0; j < 4; j++) {
                int kk = kk0 + j;
                float v = 0.f;
                if ((bn + n) < N && (k0 + kk) < K) v = B[(bn + n) * K + k0 + kk];
                Bs[kk][n] = v;
            }
        }
        __syncthreads();
        #pragma unroll
        for (int kk = 0; kk < BK; kk++) {
            float a[4], b[4];
            #pragma unroll
            for (int i = 0; i < 4; i++) a[i] = As[kk][ty + 16 * i];
            #pragma unroll
            for (int j = 0; j < 4; j++) b[j] = Bs[kk][tx + 16 * j];
            #pragma unroll
            for (int i = 0; i < 4; i++)
                #pragma unroll
                for (int j = 0; j < 4; j++)
                    acc[i][j] = fmaf(a[i], b[j], acc[i][j]);
        }
        __syncthreads();
    }

    #pragma unroll
    for (int i = 0; i < 4; i++) {
        #pragma unroll
        for (int j = 0; j < 4; j++) {
            int row = bm + ty + 16 * i;
            int col = bn + tx + 16 * j;
            if (row < M && col < N) {
                float v = acc[i][j];
                if (epi == EPI_PE) {
                    v += bias[col];
                    int t = row & (T_ - 1);
                    v += g_pe[t * D_ + col];
                } else if (epi == EPI_GELU) {
                    v += bias[col];
                    v = 0.5f * v * (1.f + erff(v * 0.70710678118654752f));
                } else if (epi == EPI_SIGMASK) {
                    v += bias[col];
                    v = 1.f / (1.f + expf(-v));
                    if (mask[row]) v = token[col];
                }
                Cm[row * N + col] = v;
            }
        }
    }
}

// ---------------- windowed-variance score: one block per (b,t) -----------------
__global__ void score_kernel() {
    int bt = blockIdx.x;
    int b = bt >> 9, t = bt & 511;
    int tid = threadIdx.x;            // 256
    int t0 = t - (WIN_ - 1); if (t0 < 0) t0 = 0;
    float denom = (float)((t + 1 < WIN_) ? (t + 1) : WIN_);
    float num = 0.f, den = 0.f;
    for (int d = tid; d < D_; d += 256) {
        float s1 = 0.f, s2 = 0.f;
        const float* p = &g_ex[((size_t)b * T_ + t0) * D_ + d];
        for (int tt = t0; tt <= t; tt++) {
            float v = *p; p += D_;
            s1 += v;
            s2 = fmaf(v, v, s2);
        }
        float m1 = s1 / denom;
        num += s2 / denom - m1 * m1;
        den += m1;
    }
    __shared__ float sn[256], sd[256];
    sn[tid] = num; sd[tid] = den; __syncthreads();
    for (int s = 128; s > 0; s >>= 1) {
        if (tid < s) { sn[tid] += sn[tid + s]; sd[tid] += sd[tid + s]; }
        __syncthreads();
    }
    if (tid == 0) g_score[bt] = sn[0] / (sd[0] + 1e-6f);
}

// ---------------- top-k via rank selection (lax.top_k stable-desc semantics) ---
// rank(i) = #{ j : v[j] > v[i]  or (v[j] == v[i] and j < i) }
// element i is selected iff rank < k, and lands at output position rank.
__global__ void topk_kernel(const float* __restrict__ vals, int n, int k,
                            int* __restrict__ idx_out,
                            unsigned char* __restrict__ mask_out,
                            float* __restrict__ outf)
{
    int b = blockIdx.x;
    int tid = threadIdx.x;            // 512
    __shared__ float v[512];
    for (int i = tid; i < n; i += blockDim.x) v[i] = vals[b * n + i];
    if (tid < n) mask_out[b * n + tid] = 0;
    __syncthreads();
    if (tid < n) {
        float x = v[tid];
        int rank = 0;
        for (int j = 0; j < n; j++) {
            float y = v[j];
            rank += (y > x) || (y == x && j < tid);
        }
        if (rank < k) {
            idx_out[b * k + rank] = tid;
            outf[b * k + rank] = (float)tid;
            mask_out[b * n + tid] = 1;
        }
    }
}

// ---------------- rfft via DFT: RF_G freqs per block, shared ex reads ----------
__global__ void rfft_kernel() {
    int nfg = (F_ + RF_G - 1) / RF_G;       // 65
    int b = blockIdx.x / nfg;
    int f0 = (blockIdx.x % nfg) * RF_G;
    int d = threadIdx.x;                    // 512
    __shared__ float ct[512], st[512];
    __shared__ float sm_mag[RF_G];
    ct[d] = g_costab[d]; st[d] = g_sintab[d];
    if (d < RF_G) sm_mag[d] = 0.f;
    __syncthreads();

    float cr[RF_G] = {}, ci[RF_G] = {};
    int idx[RF_G] = {};
    const float* p = &g_ex[(size_t)b * T_ * D_ + d];
    for (int t = 0; t < T_; t++) {
        float x = p[(size_t)t * D_];
        #pragma unroll
        for (int g = 0; g < RF_G; g++) {
            cr[g] = fmaf(x, ct[idx[g]], cr[g]);
            ci[g] = fmaf(-x, st[idx[g]], ci[g]);
            idx[g] = (idx[g] + f0 + g) & 511;
        }
    }
    #pragma unroll
    for (int g = 0; g < RF_G; g++) {
        int f = f0 + g;
        if (f < F_) {
            g_cx[((size_t)b * F_ + f) * D_ + d] = make_float2(cr[g], ci[g]);
            float m = sqrtf(cr[g] * cr[g] + ci[g] * ci[g]);
            #pragma unroll
            for (int o = 16; o > 0; o >>= 1) m += __shfl_xor_sync(0xffffffffu, m, o);
            if ((d & 31) == 0) atomicAdd(&sm_mag[g], m);
        }
    }
    __syncthreads();
    if (d < RF_G && (f0 + d) < F_) g_mag[b * F_ + f0 + d] = sm_mag[d] * (1.f / 512.f);
}

// ---------------- time-domain mask tm = irfft(fmask) != 0 ----------------------
__global__ void tm_kernel() {
    int b = blockIdx.x;
    int t = threadIdx.x;              // 512
    const unsigned char* fm = &g_fmask[b * F_];
    float y = fm[0] ? 1.f : 0.f;
    for (int f = 1; f < 256; f++)
        if (fm[f]) y += 2.f * g_costab[(f * t) & 511];
    if (fm[256]) y += (t & 1) ? -1.f : 1.f;
    g_tm[b * T_ + t] = (y != 0.f) ? 1 : 0;
}

// ---------------- masked irfft: IR_G time points per block ---------------------
// imag of DC/Nyquist ignored (C2R semantics).
__global__ void irfft_kernel(const float* __restrict__ f_tok_re,
                             const float* __restrict__ f_tok_im) {
    int ntg = T_ / IR_G;                    // 64
    int b = blockIdx.x / ntg;
    int t0 = (blockIdx.x % ntg) * IR_G;
    int d = threadIdx.x;                    // 512
    __shared__ float ct[512], st[512];
    __shared__ unsigned char fm_sm[F_];
    ct[d] = g_costab[d]; st[d] = g_sintab[d];
    if (d < F_) fm_sm[d] = g_fmask[b * F_ + d];
    __syncthreads();

    float tr = f_tok_re[d], ti = f_tok_im[d];
    const float2* cxb = &g_cx[(size_t)b * F_ * D_ + d];

    float acc[IR_G];
    {
        float re0 = fm_sm[0] ? tr : cxb[0].x;
        #pragma unroll
        for (int g = 0; g < IR_G; g++) acc[g] = re0;
    }
    int idx[IR_G] = {};
    for (int f = 1; f < 256; f++) {
        float2 c = cxb[(size_t)f * D_];
        float re, im;
        if (fm_sm[f]) { re = tr; im = ti; } else { re = c.x; im = c.y; }
        #pragma unroll
        for (int g = 0; g < IR_G; g++) {
            idx[g] = (idx[g] + t0 + g) & 511;       // idx = (f * t_g) & 511
            acc[g] += 2.f * (re * ct[idx[g]] - im * st[idx[g]]);
        }
    }
    {
        float re = fm_sm[256] ? tr : cxb[(size_t)256 * D_].x;
        #pragma unroll
        for (int g = 0; g < IR_G; g++)
            acc[g] += ((t0 + g) & 1) ? -re : re;
    }
    #pragma unroll
    for (int g = 0; g < IR_G; g++)
        g_mtd[((size_t)b * T_ + t0 + g) * D_ + d] = acc[g] * (1.f / 512.f);
}

// ---------------- out_f: mx where tm, else scalar MLP (usually dead) -----------
__global__ void outf_kernel(float* __restrict__ out,
                            const float* __restrict__ fW1, const float* __restrict__ fb1,
                            const float* __restrict__ fW2, const float* __restrict__ fb2)
{
    int i = blockIdx.x * blockDim.x + threadIdx.x;
    if (i >= B_ * T_ * C_) return;
    int bt = i / C_;
    float m = g_mx[i];
    if (g_tm[bt]) { out[i] = m; return; }
    float acc = 0.f;
    for (int dd = 0; dd < D_; dd++) {
        float u = fmaf(m, fW1[dd], fb1[dd]);
        float g = 0.5f * u * (1.f + erff(u * 0.70710678118654752f));
        acc = fmaf(g, fW2[dd], acc);
    }
    out[i] = 1.f / (1.f + expf(-(acc + fb2[0])));
}

// ---------------- launch ----------------
extern "C" void kernel_launch(void* const* d_in, const int* in_sizes, int n_in,
                              void* d_out, int out_size) {
    const float* x        = (const float*)d_in[0];
    const float* W_emb    = (const float*)d_in[1];
    const float* b_emb    = (const float*)d_in[2];
    const float* t_token  = (const float*)d_in[3];
    const float* tW1      = (const float*)d_in[4];
    const float* tb1      = (const float*)d_in[5];
    const float* tW2      = (const float*)d_in[6];
    const float* tb2      = (const float*)d_in[7];
    const float* f_tok_re = (const float*)d_in[8];
    const float* f_tok_im = (const float*)d_in[9];
    const float* fW1      = (const float*)d_in[10];
    const float* fb1      = (const float*)d_in[11];
    const float* fW2      = (const float*)d_in[12];
    const float* fb2      = (const float*)d_in[13];
    float* out = (float*)d_out;

    // output packing: out_t [B,T,D] | tidx [B,51] | out_f [B,T,C] | fidx [B,51]
    float* out_t    = out;
    float* out_tidx = out + (size_t)B_ * T_ * D_;
    float* out_f    = out_tidx + B_ * K_TOP;
    float* out_fidx = out_f + (size_t)B_ * T_ * C_;

    float *p_ex, *p_h, *p_mtd, *p_mx, *p_score, *p_mag;
    int *p_tidx, *p_fidx;
    unsigned char *p_tmask, *p_fmask;
    cudaGetSymbolAddress((void**)&p_ex,    g_ex);
    cudaGetSymbolAddress((void**)&p_h,     g_h);
    cudaGetSymbolAddress((void**)&p_mtd,   g_mtd);
    cudaGetSymbolAddress((void**)&p_mx,    g_mx);
    cudaGetSymbolAddress((void**)&p_score, g_score);
    cudaGetSymbolAddress((void**)&p_mag,   g_mag);
    cudaGetSymbolAddress((void**)&p_tidx,  g_tidx);
    cudaGetSymbolAddress((void**)&p_fidx,  g_fidx);
    cudaGetSymbolAddress((void**)&p_tmask, g_tmask);
    cudaGetSymbolAddress((void**)&p_fmask, g_fmask);

    init_div_kernel<<<1, 512>>>();
    init_pe_kernel<<<(T_ * D_ + 255) / 256, 256>>>();

    // ex = x * W_emb^T + b_emb + PE     [1024,512] K=263
    sgemm_kernel<<<dim3(512 / BN, 1024 / BM), 256>>>(
        x, W_emb, p_ex, B_ * T_, D_, C_, 0, b_emb, EPI_PE, nullptr, nullptr);

    // temporal score + top-k
    score_kernel<<<B_ * T_, 256>>>();
    topk_kernel<<<B_, 512>>>(p_score, T_, K_TOP, p_tidx, p_tmask, out_tidx);

    // h = gelu(ex * tW1^T + tb1)
    sgemm_kernel<<<dim3(512 / BN, 1024 / BM), 256>>>(
        p_ex, tW1, p_h, B_ * T_, D_, D_, 0, tb1, EPI_GELU, nullptr, nullptr);

    // out_t = tmask ? t_token : sigmoid(h * tW2^T + tb2)
    sgemm_kernel<<<dim3(512 / BN, 1024 / BM), 256>>>(
        p_h, tW2, out_t, B_ * T_, D_, D_, 0, tb2, EPI_SIGMASK, p_tmask, t_token);

    // rfft + magnitude mean, freq top-k
    {
        int nfg = (F_ + RF_G - 1) / RF_G;
        rfft_kernel<<<B_ * nfg, 512>>>();
    }
    topk_kernel<<<B_, 512>>>(p_mag, F_, K_TOP, p_fidx, p_fmask, out_fidx);

    // tm mask + masked irfft
    tm_kernel<<<B_, 512>>>();
    irfft_kernel<<<B_ * (T_ / IR_G), 512>>>(f_tok_re, f_tok_im);

    // mx = mtd * W_emb  (B is [K=D, N=C], natural layout)
    sgemm_kernel<<<dim3((C_ + BN - 1) / BN, 1024 / BM), 256>>>(
        p_mtd, W_emb, p_mx, B_ * T_, C_, D_, 1, nullptr, EPI_NONE, nullptr, nullptr);

    // out_f
    outf_kernel<<<(B_ * T_ * C_ + 255) / 256, 256>>>(out_f, fW1, fb1, fW2, fb2);
}

// round 3
// speedup vs baseline: 1.5597x; 1.1682x over previous
#include <cuda_runtime.h>
#include <math.h>

#define B_ 2
#define T_ 512
#define C_ 263
#define D_ 512
#define F_ 257          // T/2 + 1
#define K_TOP 51        // int(512 * 0.1)
#define WIN_ 24
#define KPAD 272        // 263 padded to multiple of 16 (zero-filled)

#define RF_G 4          // freqs per block in rfft
#define IR_G 8          // time points per block in irfft

// ---------------- scratch (static device memory; no allocation) ----------------
__device__ float g_ex [B_*T_*D_];
__device__ float g_h  [B_*T_*D_];
__device__ float g_mtd[B_*T_*D_];
__device__ float2 g_cx[B_*F_*D_];       // (re, im), layout [b][f][d]
__device__ float g_mx [B_*T_*C_];
__device__ float g_score[B_*T_];
__device__ float g_mag  [B_*F_];
__device__ int   g_tidx[B_*K_TOP];
__device__ int   g_fidx[B_*K_TOP];
__device__ unsigned char g_tmask[B_*T_];
__device__ unsigned char g_fmask[B_*F_];
__device__ unsigned char g_tm   [B_*T_];
__device__ float g_costab[512];
__device__ float g_sintab[512];
__device__ float g_pe[T_*D_];
__device__ double g_div[256];           // PE divisors (fp64)
__device__ float g_xpad[B_*T_*KPAD + 64];   // x zero-padded to K=272
__device__ float g_wpad[D_*KPAD + 64];      // W_emb zero-padded to 272 cols

// ---------------- stream/event (created in static ctor, pre-checkpoint) --------
static cudaStream_t g_sB = nullptr;
static cudaEvent_t g_evFork = nullptr, g_evJoin = nullptr;
namespace {
struct StreamInit {
    StreamInit() {
        cudaStreamCreateWithFlags(&g_sB, cudaStreamNonBlocking);
        cudaEventCreateWithFlags(&g_evFork, cudaEventDisableTiming);
        cudaEventCreateWithFlags(&g_evJoin, cudaEventDisableTiming);
    }
};
StreamInit g_streamInit;
}

// ---------------- table init ----------------------------------------------------
__global__ void init_div_kernel() {
    int i = threadIdx.x;                 // 512 threads
    if (i < 256) {
        g_div[i] = exp(-(double)(2 * i) * (9.210340371976184 / 512.0));
    }
    if (i < 512) {
        float s, c;
        sincospif((float)i / 256.0f, &s, &c);   // 2*pi*i/512
        g_costab[i] = c; g_sintab[i] = s;
    }
}

__global__ void init_pe_kernel() {
    int i = blockIdx.x * blockDim.x + threadIdx.x;
    if (i >= T_ * D_) return;
    int t = i / D_, d = i % D_;
    double arg = (double)t * g_div[d >> 1];
    const double PI2 = 6.283185307179586476925286766559;
    double q = rint(arg * (1.0 / PI2));
    float rf = (float)(arg - q * PI2);
    g_pe[i] = (d & 1) ? cosf(rf) : sinf(rf);
}

// pad copy: dst[row][0..262]=src, [263..271]=0
__global__ void pad_kernel(const float* __restrict__ src, float* __restrict__ dst, int rows) {
    int i = blockIdx.x * blockDim.x + threadIdx.x;
    if (i >= rows * KPAD) return;
    int r = i / KPAD, c = i % KPAD;
    dst[i] = (c < C_) ? src[r * C_ + c] : 0.f;
}

// ---------------- SGEMM v2: 64x64x16 tile, 128 threads, 8x4/thread, float4 -----
#define EPI_NONE    0
#define EPI_PE      2
#define EPI_GELU    3
#define EPI_SIGMASK 4

// C[M=1024, N] = A[1024, K](lda) * B(^T).  K multiple of 16, M multiple of 64.
// bKN=0: B is [N][K] row-major (ldb = row stride)  -> A*B^T
// bKN=1: B is [K][ldb] row-major, logical [K][N]   -> A*B
__global__ void __launch_bounds__(128) sgemm2_kernel(
        const float* __restrict__ A, int lda,
        const float* __restrict__ B, int ldb, int bKN,
        float* __restrict__ Cm, int ldc, int N, int K,
        const float* __restrict__ bias, int epi,
        const unsigned char* __restrict__ mask,
        const float* __restrict__ token)
{
    __shared__ float As[16][64];
    __shared__ float Bs[16][64];
    int tid = threadIdx.x;            // 128
    int bm = blockIdx.y * 64;
    int bn = blockIdx.x * 64;
    int m0 = (tid >> 4) * 8;          // 0..56
    int n0 = (tid & 15) * 4;          // 0..60
    float acc[8][4] = {};

    for (int k0 = 0; k0 < K; k0 += 16) {
        #pragma unroll
        for (int j = 0; j < 2; j++) {
            int i = tid + j * 128;
            int row = i >> 2, kq = (i & 3) * 4;
            float4 v = *(const float4*)&A[(size_t)(bm + row) * lda + k0 + kq];
            As[kq + 0][row] = v.x; As[kq + 1][row] = v.y;
            As[kq + 2][row] = v.z; As[kq + 3][row] = v.w;
        }
        if (bKN) {
            #pragma unroll
            for (int j = 0; j < 2; j++) {
                int i = tid + j * 128;
                int kk = i >> 4, nn = (i & 15) * 4;
                float4 v = make_float4(0.f, 0.f, 0.f, 0.f);
                if (bn + nn < ldb)
                    v = *(const float4*)&B[(size_t)(k0 + kk) * ldb + bn + nn];
                *(float4*)&Bs[kk][nn] = v;
            }
        } else {
            #pragma unroll
            for (int j = 0; j < 2; j++) {
                int i = tid + j * 128;
                int row = i >> 2, kq = (i & 3) * 4;
                float4 v = *(const float4*)&B[(size_t)(bn + row) * ldb + k0 + kq];
                Bs[kq + 0][row] = v.x; Bs[kq + 1][row] = v.y;
                Bs[kq + 2][row] = v.z; Bs[kq + 3][row] = v.w;
            }
        }
        __syncthreads();
        #pragma unroll
        for (int kk = 0; kk < 16; kk++) {
            float4 a0 = *(const float4*)&As[kk][m0];
            float4 a1 = *(const float4*)&As[kk][m0 + 4];
            float4 b  = *(const float4*)&Bs[kk][n0];
            float am[8] = {a0.x, a0.y, a0.z, a0.w, a1.x, a1.y, a1.z, a1.w};
            float bn_[4] = {b.x, b.y, b.z, b.w};
            #pragma unroll
            for (int i = 0; i < 8; i++)
                #pragma unroll
                for (int j = 0; j < 4; j++)
                    acc[i][j] = fmaf(am[i], bn_[j], acc[i][j]);
        }
        __syncthreads();
    }

    bool vec = ((N & 3) == 0);
    #pragma unroll
    for (int i = 0; i < 8; i++) {
        int row = bm + m0 + i;
        float v4[4];
        #pragma unroll
        for (int j = 0; j < 4; j++) {
            int col = bn + n0 + j;
            float v = acc[i][j];
            if (epi == EPI_PE) {
                v += bias[col];
                v += g_pe[(row & (T_ - 1)) * D_ + col];
            } else if (epi == EPI_GELU) {
                v += bias[col];
                v = 0.5f * v * (1.f + erff(v * 0.70710678118654752f));
            } else if (epi == EPI_SIGMASK) {
                v += bias[col];
                v = 1.f / (1.f + expf(-v));
                if (mask[row]) v = token[col];
            }
            v4[j] = v;
        }
        if (vec) {
            *(float4*)&Cm[(size_t)row * ldc + bn + n0] =
                make_float4(v4[0], v4[1], v4[2], v4[3]);
        } else {
            #pragma unroll
            for (int j = 0; j < 4; j++) {
                int col = bn + n0 + j;
                if (col < N) Cm[(size_t)row * ldc + col] = v4[j];
            }
        }
    }
}

// ---------------- windowed-variance score: one block per (b,t) -----------------
__global__ void score_kernel() {
    int bt = blockIdx.x;
    int b = bt >> 9, t = bt & 511;
    int tid = threadIdx.x;            // 256
    int t0 = t - (WIN_ - 1); if (t0 < 0) t0 = 0;
    float denom = (float)((t + 1 < WIN_) ? (t + 1) : WIN_);
    float num = 0.f, den = 0.f;
    for (int d = tid; d < D_; d += 256) {
        float s1 = 0.f, s2 = 0.f;
        const float* p = &g_ex[((size_t)b * T_ + t0) * D_ + d];
        for (int tt = t0; tt <= t; tt++) {
            float v = *p; p += D_;
            s1 += v;
            s2 = fmaf(v, v, s2);
        }
        float m1 = s1 / denom;
        num += s2 / denom - m1 * m1;
        den += m1;
    }
    __shared__ float sn[256], sd[256];
    sn[tid] = num; sd[tid] = den; __syncthreads();
    for (int s = 128; s > 0; s >>= 1) {
        if (tid < s) { sn[tid] += sn[tid + s]; sd[tid] += sd[tid + s]; }
        __syncthreads();
    }
    if (tid == 0) g_score[bt] = sn[0] / (sd[0] + 1e-6f);
}

// ---------------- top-k via rank selection (lax.top_k stable-desc semantics) ---
__global__ void topk_kernel(const float* __restrict__ vals, int n, int k,
                            int* __restrict__ idx_out,
                            unsigned char* __restrict__ mask_out,
                            float* __restrict__ outf)
{
    int b = blockIdx.x;
    int tid = threadIdx.x;            // 512
    __shared__ float v[512];
    for (int i = tid; i < n; i += blockDim.x) v[i] = vals[b * n + i];
    if (tid < n) mask_out[b * n + tid] = 0;
    __syncthreads();
    if (tid < n) {
        float x = v[tid];
        int rank = 0;
        for (int j = 0; j < n; j++) {
            float y = v[j];
            rank += (y > x) || (y == x && j < tid);
        }
        if (rank < k) {
            idx_out[b * k + rank] = tid;
            outf[b * k + rank] = (float)tid;
            mask_out[b * n + tid] = 1;
        }
    }
}

// ---------------- rfft via DFT: RF_G freqs per block, shared ex reads ----------
__global__ void rfft_kernel() {
    int nfg = (F_ + RF_G - 1) / RF_G;       // 65
    int b = blockIdx.x / nfg;
    int f0 = (blockIdx.x % nfg) * RF_G;
    int d = threadIdx.x;                    // 512
    __shared__ float ct[512], st[512];
    __shared__ float sm_mag[RF_G];
    ct[d] = g_costab[d]; st[d] = g_sintab[d];
    if (d < RF_G) sm_mag[d] = 0.f;
    __syncthreads();

    float cr[RF_G] = {}, ci[RF_G] = {};
    int idx[RF_G] = {};
    const float* p = &g_ex[(size_t)b * T_ * D_ + d];
    for (int t = 0; t < T_; t++) {
        float x = p[(size_t)t * D_];
        #pragma unroll
        for (int g = 0; g < RF_G; g++) {
            cr[g] = fmaf(x, ct[idx[g]], cr[g]);
            ci[g] = fmaf(-x, st[idx[g]], ci[g]);
            idx[g] = (idx[g] + f0 + g) & 511;
        }
    }
    #pragma unroll
    for (int g = 0; g < RF_G; g++) {
        int f = f0 + g;
        if (f < F_) {
            g_cx[((size_t)b * F_ + f) * D_ + d] = make_float2(cr[g], ci[g]);
            float m = sqrtf(cr[g] * cr[g] + ci[g] * ci[g]);
            #pragma unroll
            for (int o = 16; o > 0; o >>= 1) m += __shfl_xor_sync(0xffffffffu, m, o);
            if ((d & 31) == 0) atomicAdd(&sm_mag[g], m);
        }
    }
    __syncthreads();
    if (d < RF_G && (f0 + d) < F_) g_mag[b * F_ + f0 + d] = sm_mag[d] * (1.f / 512.f);
}

// ---------------- time-domain mask tm = irfft(fmask) != 0 ----------------------
__global__ void tm_kernel() {
    int b = blockIdx.x;
    int t = threadIdx.x;              // 512
    const unsigned char* fm = &g_fmask[b * F_];
    float y = fm[0] ? 1.f : 0.f;
    for (int f = 1; f < 256; f++)
        if (fm[f]) y += 2.f * g_costab[(f * t) & 511];
    if (fm[256]) y += (t & 1) ? -1.f : 1.f;
    g_tm[b * T_ + t] = (y != 0.f) ? 1 : 0;
}

// ---------------- masked irfft: IR_G time points per block ---------------------
__global__ void irfft_kernel(const float* __restrict__ f_tok_re,
                             const float* __restrict__ f_tok_im) {
    int ntg = T_ / IR_G;                    // 64
    int b = blockIdx.x / ntg;
    int t0 = (blockIdx.x % ntg) * IR_G;
    int d = threadIdx.x;                    // 512
    __shared__ float ct[512], st[512];
    __shared__ unsigned char fm_sm[F_];
    ct[d] = g_costab[d]; st[d] = g_sintab[d];
    if (d < F_) fm_sm[d] = g_fmask[b * F_ + d];
    __syncthreads();

    float tr = f_tok_re[d], ti = f_tok_im[d];
    const float2* cxb = &g_cx[(size_t)b * F_ * D_ + d];

    float acc[IR_G];
    {
        float re0 = fm_sm[0] ? tr : cxb[0].x;
        #pragma unroll
        for (int g = 0; g < IR_G; g++) acc[g] = re0;
    }
    int idx[IR_G] = {};
    for (int f = 1; f < 256; f++) {
        float2 c = cxb[(size_t)f * D_];
        float re, im;
        if (fm_sm[f]) { re = tr; im = ti; } else { re = c.x; im = c.y; }
        #pragma unroll
        for (int g = 0; g < IR_G; g++) {
            idx[g] = (idx[g] + t0 + g) & 511;       // idx = (f * t_g) & 511
            acc[g] += 2.f * (re * ct[idx[g]] - im * st[idx[g]]);
        }
    }
    {
        float re = fm_sm[256] ? tr : cxb[(size_t)256 * D_].x;
        #pragma unroll
        for (int g = 0; g < IR_G; g++)
            acc[g] += ((t0 + g) & 1) ? -re : re;
    }
    #pragma unroll
    for (int g = 0; g < IR_G; g++)
        g_mtd[((size_t)b * T_ + t0 + g) * D_ + d] = acc[g] * (1.f / 512.f);
}

// ---------------- out_f: mx where tm, else scalar MLP (usually dead) -----------
__global__ void outf_kernel(float* __restrict__ out,
                            const float* __restrict__ fW1, const float* __restrict__ fb1,
                            const float* __restrict__ fW2, const float* __restrict__ fb2)
{
    int i = blockIdx.x * blockDim.x + threadIdx.x;
    if (i >= B_ * T_ * C_) return;
    int bt = i / C_;
    float m = g_mx[i];
    if (g_tm[bt]) { out[i] = m; return; }
    float acc = 0.f;
    for (int dd = 0; dd < D_; dd++) {
        float u = fmaf(m, fW1[dd], fb1[dd]);
        float g = 0.5f * u * (1.f + erff(u * 0.70710678118654752f));
        acc = fmaf(g, fW2[dd], acc);
    }
    out[i] = 1.f / (1.f + expf(-(acc + fb2[0])));
}

// ---------------- launch ----------------
extern "C" void kernel_launch(void* const* d_in, const int* in_sizes, int n_in,
                              void* d_out, int out_size) {
    const float* x        = (const float*)d_in[0];
    const float* W_emb    = (const float*)d_in[1];
    const float* b_emb    = (const float*)d_in[2];
    const float* t_token  = (const float*)d_in[3];
    const float* tW1      = (const float*)d_in[4];
    const float* tb1      = (const float*)d_in[5];
    const float* tW2      = (const float*)d_in[6];
    const float* tb2      = (const float*)d_in[7];
    const float* f_tok_re = (const float*)d_in[8];
    const float* f_tok_im = (const float*)d_in[9];
    const float* fW1      = (const float*)d_in[10];
    const float* fb1      = (const float*)d_in[11];
    const float* fW2      = (const float*)d_in[12];
    const float* fb2      = (const float*)d_in[13];
    float* out = (float*)d_out;

    // output packing: out_t [B,T,D] | tidx [B,51] | out_f [B,T,C] | fidx [B,51]
    float* out_t    = out;
    float* out_tidx = out + (size_t)B_ * T_ * D_;
    float* out_f    = out_tidx + B_ * K_TOP;
    float* out_fidx = out_f + (size_t)B_ * T_ * C_;

    float *p_ex, *p_h, *p_mtd, *p_mx, *p_score, *p_mag, *p_xpad, *p_wpad;
    int *p_tidx, *p_fidx;
    unsigned char *p_tmask, *p_fmask;
    cudaGetSymbolAddress((void**)&p_ex,    g_ex);
    cudaGetSymbolAddress((void**)&p_h,     g_h);
    cudaGetSymbolAddress((void**)&p_mtd,   g_mtd);
    cudaGetSymbolAddress((void**)&p_mx,    g_mx);
    cudaGetSymbolAddress((void**)&p_score, g_score);
    cudaGetSymbolAddress((void**)&p_mag,   g_mag);
    cudaGetSymbolAddress((void**)&p_xpad,  g_xpad);
    cudaGetSymbolAddress((void**)&p_wpad,  g_wpad);
    cudaGetSymbolAddress((void**)&p_tidx,  g_tidx);
    cudaGetSymbolAddress((void**)&p_fidx,  g_fidx);
    cudaGetSymbolAddress((void**)&p_tmask, g_tmask);
    cudaGetSymbolAddress((void**)&p_fmask, g_fmask);

    // fallback if static ctor didn't run in a usable context
    if (!g_sB) {
        cudaStreamCreateWithFlags(&g_sB, cudaStreamNonBlocking);
        cudaEventCreateWithFlags(&g_evFork, cudaEventDisableTiming);
        cudaEventCreateWithFlags(&g_evJoin, cudaEventDisableTiming);
    }

    // ---- prologue on stream 0 ----
    init_div_kernel<<<1, 512>>>();
    init_pe_kernel<<<(T_ * D_ + 255) / 256, 256>>>();
    pad_kernel<<<(B_ * T_ * KPAD + 255) / 256, 256>>>(x, p_xpad, B_ * T_);
    pad_kernel<<<(D_ * KPAD + 255) / 256, 256>>>(W_emb, p_wpad, D_);

    // ex = x * W_emb^T + b_emb + PE      (padded K=272)
    sgemm2_kernel<<<dim3(D_ / 64, B_ * T_ / 64), 128>>>(
        p_xpad, KPAD, p_wpad, KPAD, 0, p_ex, D_, D_, KPAD,
        b_emb, EPI_PE, nullptr, nullptr);

    // ---- fork: path B (frequency) on g_sB ----
    cudaEventRecord(g_evFork, 0);
    cudaStreamWaitEvent(g_sB, g_evFork, 0);
    {
        int nfg = (F_ + RF_G - 1) / RF_G;
        rfft_kernel<<<B_ * nfg, 512, 0, g_sB>>>();
        topk_kernel<<<B_, 512, 0, g_sB>>>(p_mag, F_, K_TOP, p_fidx, p_fmask, out_fidx);
        tm_kernel<<<B_, 512, 0, g_sB>>>();
        irfft_kernel<<<B_ * (T_ / IR_G), 512, 0, g_sB>>>(f_tok_re, f_tok_im);
        // mx = mtd * W_emb  (B = wpad [K=512 rows][272 cols], logical N=263)
        sgemm2_kernel<<<dim3((C_ + 63) / 64, B_ * T_ / 64), 128, 0, g_sB>>>(
            p_mtd, D_, p_wpad, KPAD, 1, p_mx, C_, C_, D_,
            nullptr, EPI_NONE, nullptr, nullptr);
        outf_kernel<<<(B_ * T_ * C_ + 255) / 256, 256, 0, g_sB>>>(out_f, fW1, fb1, fW2, fb2);
        cudaEventRecord(g_evJoin, g_sB);
    }

    // ---- path A (temporal) on stream 0 ----
    score_kernel<<<B_ * T_, 256>>>();
    topk_kernel<<<B_, 512>>>(p_score, T_, K_TOP, p_tidx, p_tmask, out_tidx);
    // h = gelu(ex * tW1^T + tb1)
    sgemm2_kernel<<<dim3(D_ / 64, B_ * T_ / 64), 128>>>(
        p_ex, D_, tW1, D_, 0, p_h, D_, D_, D_,
        tb1, EPI_GELU, nullptr, nullptr);
    // out_t = tmask ? t_token : sigmoid(h * tW2^T + tb2)
    sgemm2_kernel<<<dim3(D_ / 64, B_ * T_ / 64), 128>>>(
        p_h, D_, tW2, D_, 0, out_t, D_, D_, D_,
        tb2, EPI_SIGMASK, p_tmask, t_token);

    // ---- join ----
    cudaStreamWaitEvent(0, g_evJoin, 0);
}

// round 5
// speedup vs baseline: 1.9701x; 1.2632x over previous
#include <cuda_runtime.h>
#include <math.h>

#define B_ 2
#define T_ 512
#define C_ 263
#define D_ 512
#define F_ 257          // T/2 + 1
#define K_TOP 51        // int(512 * 0.1)
#define WIN_ 24
#define KPAD 272        // 263 padded to multiple of 16 (zero-filled)

#define MR 640          // rfft GEMM M: 320 cos rows + 320 sin rows
#define KI 544          // irfft GEMM K: 272 re rows + 272 im rows

// ---------------- scratch (static device memory; no allocation) ----------------
__device__ float g_ex [B_*T_*D_];
__device__ float g_h  [B_*T_*D_];
__device__ float g_mtd[B_*T_*D_];
__device__ float g_cf [B_*MR*D_];       // per b: rows 0..256 = re, rows 320..576 = im
__device__ float g_fin[B_*KI*D_];       // per b: rows 0..271 = masked re, 272..543 = masked im
__device__ float g_score[B_*T_];
__device__ float g_mag  [B_*F_];
__device__ int   g_tidx[B_*K_TOP];
__device__ int   g_fidx[B_*K_TOP];
__device__ unsigned char g_tmask[B_*T_];
__device__ unsigned char g_fmask[B_*F_];
__device__ unsigned char g_tm   [B_*T_];
__device__ float g_costab[512];
__device__ float g_sintab[512];
__device__ float g_pe[T_*D_];
__device__ double g_div[256];           // PE divisors (fp64)
__device__ float g_xpad[B_*T_*KPAD + 64];   // x zero-padded to K=272
__device__ float g_wpad[D_*KPAD + 64];      // W_emb zero-padded to 272 cols
__device__ float g_wdft [MR*D_];        // rfft weights  [640][512]
__device__ float g_widft[T_*KI];        // irfft weights [512][544]

// ---------------- stream/event (created in static ctor, pre-checkpoint) --------
static cudaStream_t g_sB = nullptr;
static cudaEvent_t g_evStart = nullptr, g_evFork = nullptr, g_evJoin = nullptr;
namespace {
struct StreamInit {
    StreamInit() {
        cudaStreamCreateWithFlags(&g_sB, cudaStreamNonBlocking);
        cudaEventCreateWithFlags(&g_evStart, cudaEventDisableTiming);
        cudaEventCreateWithFlags(&g_evFork, cudaEventDisableTiming);
        cudaEventCreateWithFlags(&g_evJoin, cudaEventDisableTiming);
    }
};
StreamInit g_streamInit;
}

// ---------------- table init ----------------------------------------------------
__global__ void init_div_kernel() {
    int i = threadIdx.x;                 // 512 threads
    if (i < 256) {
        g_div[i] = exp(-(double)(2 * i) * (9.210340371976184 / 512.0));
    }
    if (i < 512) {
        float s, c;
        sincospif((float)i / 256.0f, &s, &c);   // 2*pi*i/512
        g_costab[i] = c; g_sintab[i] = s;
    }
}

__global__ void init_pe_kernel() {
    int i = blockIdx.x * blockDim.x + threadIdx.x;
    if (i >= T_ * D_) return;
    int t = i / D_, d = i % D_;
    double arg = (double)t * g_div[d >> 1];
    const double PI2 = 6.283185307179586476925286766559;
    double q = rint(arg * (1.0 / PI2));
    float rf = (float)(arg - q * PI2);
    g_pe[i] = (d & 1) ? cosf(rf) : sinf(rf);
}

// DFT weight tables (input-independent; computed with identical twiddles)
__global__ void init_wdft_kernel() {
    int i = blockIdx.x * blockDim.x + threadIdx.x;
    const int n1 = MR * D_;
    if (i < n1) {
        int r = i >> 9, t = i & 511;
        float v = 0.f;
        if (r < F_) {                       // cos row, f = r
            float s, c; sincospif((float)((r * t) & 511) / 256.0f, &s, &c);
            v = c;
        } else if (r >= 320 && r < 320 + F_) {  // -sin row, f = r-320
            float s, c; sincospif((float)(((r - 320) * t) & 511) / 256.0f, &s, &c);
            v = -s;
        }
        g_wdft[i] = v;
    } else {
        int j = i - n1;
        if (j < T_ * KI) {
            int t = j / KI, c = j % KI;
            float v = 0.f;
            if (c < F_) {                   // re weight, f = c
                float w = (c == 0 || c == 256) ? (1.f / 512.f) : (2.f / 512.f);
                float s, cc; sincospif((float)((c * t) & 511) / 256.0f, &s, &cc);
                v = w * cc;
            } else if (c >= 272 && c < 272 + F_) {  // im weight, f = c-272
                int f = c - 272;
                if (f >= 1 && f <= 255) {   // DC/Nyquist imag ignored (C2R)
                    float s, cc; sincospif((float)((f * t) & 511) / 256.0f, &s, &cc);
                    v = -(2.f / 512.f) * s;
                }
            }
            g_widft[j] = v;
        }
    }
}

// pad x -> [B*T][272] and W_emb -> [D][272] in one kernel
__global__ void pad_kernel(const float* __restrict__ x, const float* __restrict__ w) {
    int i = blockIdx.x * blockDim.x + threadIdx.x;
    const int n1 = B_ * T_ * KPAD;
    if (i < n1) {
        int r = i / KPAD, c = i % KPAD;
        g_xpad[i] = (c < C_) ? x[r * C_ + c] : 0.f;
    } else {
        int j = i - n1;
        if (j < D_ * KPAD) {
            int r = j / KPAD, c = j % KPAD;
            g_wpad[j] = (c < C_) ? w[r * C_ + c] : 0.f;
        }
    }
}

// ---------------- SGEMM: 64x64x16 tile, 128 threads, 8x4/thread, float4 --------
#define EPI_NONE    0
#define EPI_PE      2
#define EPI_GELU    3
#define EPI_SIGMASK 4
#define EPI_TMSEL   5

// C[M, N] = A[M, K](lda) * B(^T).  K mult of 16, M mult of 64 (per batch).
// bKN=0: B is [N][K] row-major (ldb = row stride)  -> A*B^T
// bKN=1: B is [K][ldb] row-major, logical [K][N]   -> A*B
// blockIdx.z batches: A += z*sA, B += z*sB, C += z*sC.
template <int EPI, int BKN>
__global__ void __launch_bounds__(128) sgemm2_kernel(
        const float* __restrict__ A, int lda, long sA,
        const float* __restrict__ B, int ldb, long sB,
        float* __restrict__ Cm, int ldc, long sC, int N, int K,
        const float* __restrict__ bias,
        const unsigned char* __restrict__ mask,
        const float* __restrict__ token,
        const float* __restrict__ e1, const float* __restrict__ e2,
        const float* __restrict__ e3, const float* __restrict__ e4)
{
    A += (long)blockIdx.z * sA;
    B += (long)blockIdx.z * sB;
    Cm += (long)blockIdx.z * sC;
    __shared__ float As[16][64];
    __shared__ float Bs[16][64];
    int tid = threadIdx.x;            // 128
    int bm = blockIdx.y * 64;
    int bn = blockIdx.x * 64;
    int m0 = (tid >> 4) * 8;          // 0..56
    int n0 = (tid & 15) * 4;          // 0..60
    float acc[8][4] = {};

    for (int k0 = 0; k0 < K; k0 += 16) {
        #pragma unroll
        for (int j = 0; j < 2; j++) {
            int i = tid + j * 128;
            int row = i >> 2, kq = (i & 3) * 4;
            float4 v = *(const float4*)&A[(size_t)(bm + row) * lda + k0 + kq];
            As[kq + 0][row] = v.x; As[kq + 1][row] = v.y;
            As[kq + 2][row] = v.z; As[kq + 3][row] = v.w;
        }
        if (BKN) {
            #pragma unroll
            for (int j = 0; j < 2; j++) {
                int i = tid + j * 128;
                int kk = i >> 4, nn = (i & 15) * 4;
                float4 v = make_float4(0.f, 0.f, 0.f, 0.f);
                if (bn + nn < ldb)
                    v = *(const float4*)&B[(size_t)(k0 + kk) * ldb + bn + nn];
                *(float4*)&Bs[kk][nn] = v;
            }
        } else {
            #pragma unroll
            for (int j = 0; j < 2; j++) {
                int i = tid + j * 128;
                int row = i >> 2, kq = (i & 3) * 4;
                float4 v = *(const float4*)&B[(size_t)(bn + row) * ldb + k0 + kq];
                Bs[kq + 0][row] = v.x; Bs[kq + 1][row] = v.y;
                Bs[kq + 2][row] = v.z; Bs[kq + 3][row] = v.w;
            }
        }
        __syncthreads();
        #pragma unroll
        for (int kk = 0; kk < 16; kk++) {
            float4 a0 = *(const float4*)&As[kk][m0];
            float4 a1 = *(const float4*)&As[kk][m0 + 4];
            float4 b  = *(const float4*)&Bs[kk][n0];
            float am[8] = {a0.x, a0.y, a0.z, a0.w, a1.x, a1.y, a1.z, a1.w};
            float bn_[4] = {b.x, b.y, b.z, b.w};
            #pragma unroll
            for (int i = 0; i < 8; i++)
                #pragma unroll
                for (int j = 0; j < 4; j++)
                    acc[i][j] = fmaf(am[i], bn_[j], acc[i][j]);
        }
        __syncthreads();
    }

    const bool vec = ((N & 3) == 0);
    #pragma unroll
    for (int i = 0; i < 8; i++) {
        int row = bm + m0 + i;
        float v4[4];
        #pragma unroll
        for (int j = 0; j < 4; j++) {
            int col = bn + n0 + j;
            float v = acc[i][j];
            if (EPI == EPI_PE) {
                v += bias[col];
                v += g_pe[(row & (T_ - 1)) * D_ + col];
            } else if (EPI == EPI_GELU) {
                v += bias[col];
                v = 0.5f * v * (1.f + erff(v * 0.70710678118654752f));
            } else if (EPI == EPI_SIGMASK) {
                v += bias[col];
                v = 1.f / (1.f + expf(-v));
                if (mask[row]) v = token[col];
            } else if (EPI == EPI_TMSEL) {
                // out_f: keep mx where tm, else per-element scalar MLP (usually dead)
                if (!mask[row]) {
                    float m = v, a = 0.f;
                    for (int dd = 0; dd < D_; dd++) {
                        float u = fmaf(m, e1[dd], e2[dd]);
                        float g = 0.5f * u * (1.f + erff(u * 0.70710678118654752f));
                        a = fmaf(g, e3[dd], a);
                    }
                    v = 1.f / (1.f + expf(-(a + e4[0])));
                }
            }
            v4[j] = v;
        }
        if (vec) {
            *(float4*)&Cm[(size_t)row * ldc + bn + n0] =
                make_float4(v4[0], v4[1], v4[2], v4[3]);
        } else {
            #pragma unroll
            for (int j = 0; j < 4; j++) {
                int col = bn + n0 + j;
                if (col < N) Cm[(size_t)row * ldc + col] = v4[j];
            }
        }
    }
}

// ---------------- windowed-variance score: one block per (b,t) -----------------
__global__ void score_kernel() {
    int bt = blockIdx.x;
    int b = bt >> 9, t = bt & 511;
    int tid = threadIdx.x;            // 256
    int t0 = t - (WIN_ - 1); if (t0 < 0) t0 = 0;
    float denom = (float)((t + 1 < WIN_) ? (t + 1) : WIN_);
    float num = 0.f, den = 0.f;
    for (int d = tid; d < D_; d += 256) {
        float s1 = 0.f, s2 = 0.f;
        const float* p = &g_ex[((size_t)b * T_ + t0) * D_ + d];
        for (int tt = t0; tt <= t; tt++) {
            float v = *p; p += D_;
            s1 += v;
            s2 = fmaf(v, v, s2);
        }
        float m1 = s1 / denom;
        num += s2 / denom - m1 * m1;
        den += m1;
    }
    __shared__ float sn[256], sd[256];
    sn[tid] = num; sd[tid] = den; __syncthreads();
    for (int s = 128; s > 0; s >>= 1) {
        if (tid < s) { sn[tid] += sn[tid + s]; sd[tid] += sd[tid + s]; }
        __syncthreads();
    }
    if (tid == 0) g_score[bt] = sn[0] / (sd[0] + 1e-6f);
}

// ---------------- top-k via rank selection (lax.top_k stable-desc semantics) ---
__global__ void topk_kernel(const float* __restrict__ vals, int n, int k,
                            int* __restrict__ idx_out,
                            unsigned char* __restrict__ mask_out,
                            float* __restrict__ outf)
{
    int b = blockIdx.x;
    int tid = threadIdx.x;            // 512
    __shared__ float v[512];
    for (int i = tid; i < n; i += blockDim.x) v[i] = vals[b * n + i];
    if (tid < n) mask_out[b * n + tid] = 0;
    __syncthreads();
    if (tid < n) {
        float x = v[tid];
        int rank = 0;
        for (int j = 0; j < n; j++) {
            float y = v[j];
            rank += (y > x) || (y == x && j < tid);
        }
        if (rank < k) {
            idx_out[b * k + rank] = tid;
            outf[b * k + rank] = (float)tid;
            mask_out[b * n + tid] = 1;
        }
    }
}

// ---------------- magnitude mean over d: one block per (b,f) -------------------
__global__ void mag_kernel() {
    int bf = blockIdx.x;
    int b = bf / F_, f = bf % F_;
    int d = threadIdx.x;              // 512
    float cr = g_cf[((size_t)b * MR + f) * D_ + d];
    float ci = g_cf[((size_t)b * MR + 320 + f) * D_ + d];
    float m = sqrtf(cr * cr + ci * ci);
    __shared__ float red[512];
    red[d] = m; __syncthreads();
    for (int s = 256; s > 0; s >>= 1) {
        if (d < s) red[d] += red[d + s];
        __syncthreads();
    }
    if (d == 0) g_mag[bf] = red[0] * (1.f / 512.f);
}

// ---------------- time-domain mask tm = irfft(fmask) != 0 ----------------------
__global__ void tm_kernel() {
    int b = blockIdx.x;
    int t = threadIdx.x;              // 512
    const unsigned char* fm = &g_fmask[b * F_];
    float y = fm[0] ? 1.f : 0.f;
    for (int f = 1; f < 256; f++)
        if (fm[f]) y += 2.f * g_costab[(f * t) & 511];
    if (fm[256]) y += (t & 1) ? -1.f : 1.f;
    g_tm[b * T_ + t] = (y != 0.f) ? 1 : 0;
}

// ---------------- build masked stacked spectrum for irfft GEMM -----------------
__global__ void buildfin_kernel(const float* __restrict__ f_tok_re,
                                const float* __restrict__ f_tok_im) {
    int i = blockIdx.x * blockDim.x + threadIdx.x;
    if (i >= B_ * KI * D_) return;
    int b = i / (KI * D_);
    int rem = i - b * KI * D_;
    int r = rem / D_, d = rem - r * D_;
    float v = 0.f;
    if (r < 272) {
        if (r < F_)
            v = g_fmask[b * F_ + r] ? f_tok_re[d]
                                    : g_cf[((size_t)b * MR + r) * D_ + d];
    } else {
        int f = r - 272;
        if (f < F_)
            v = g_fmask[b * F_ + f] ? f_tok_im[d]
                                    : g_cf[((size_t)b * MR + 320 + f) * D_ + d];
    }
    g_fin[i] = v;
}

// ---------------- launch ----------------
extern "C" void kernel_launch(void* const* d_in, const int* in_sizes, int n_in,
                              void* d_out, int out_size) {
    const float* x        = (const float*)d_in[0];
    const float* W_emb    = (const float*)d_in[1];
    const float* b_emb    = (const float*)d_in[2];
    const float* t_token  = (const float*)d_in[3];
    const float* tW1      = (const float*)d_in[4];
    const float* tb1      = (const float*)d_in[5];
    const float* tW2      = (const float*)d_in[6];
    const float* tb2      = (const float*)d_in[7];
    const float* f_tok_re = (const float*)d_in[8];
    const float* f_tok_im = (const float*)d_in[9];
    const float* fW1      = (const float*)d_in[10];
    const float* fb1      = (const float*)d_in[11];
    const float* fW2      = (const float*)d_in[12];
    const float* fb2      = (const float*)d_in[13];
    float* out = (float*)d_out;

    // output packing: out_t [B,T,D] | tidx [B,51] | out_f [B,T,C] | fidx [B,51]
    float* out_t    = out;
    float* out_tidx = out + (size_t)B_ * T_ * D_;
    float* out_f    = out_tidx + B_ * K_TOP;
    float* out_fidx = out_f + (size_t)B_ * T_ * C_;

    float *p_ex, *p_h, *p_mtd, *p_score, *p_mag, *p_xpad, *p_wpad;
    float *p_wdft, *p_widft, *p_cf, *p_fin;
    int *p_tidx, *p_fidx;
    unsigned char *p_tmask, *p_fmask, *p_tm;
    cudaGetSymbolAddress((void**)&p_ex,    g_ex);
    cudaGetSymbolAddress((void**)&p_h,     g_h);
    cudaGetSymbolAddress((void**)&p_mtd,   g_mtd);
    cudaGetSymbolAddress((void**)&p_score, g_score);
    cudaGetSymbolAddress((void**)&p_mag,   g_mag);
    cudaGetSymbolAddress((void**)&p_xpad,  g_xpad);
    cudaGetSymbolAddress((void**)&p_wpad,  g_wpad);
    cudaGetSymbolAddress((void**)&p_wdft,  g_wdft);
    cudaGetSymbolAddress((void**)&p_widft, g_widft);
    cudaGetSymbolAddress((void**)&p_cf,    g_cf);
    cudaGetSymbolAddress((void**)&p_fin,   g_fin);
    cudaGetSymbolAddress((void**)&p_tidx,  g_tidx);
    cudaGetSymbolAddress((void**)&p_fidx,  g_fidx);
    cudaGetSymbolAddress((void**)&p_tmask, g_tmask);
    cudaGetSymbolAddress((void**)&p_fmask, g_fmask);
    cudaGetSymbolAddress((void**)&p_tm,    g_tm);

    if (!g_sB) {
        cudaStreamCreateWithFlags(&g_sB, cudaStreamNonBlocking);
        cudaEventCreateWithFlags(&g_evStart, cudaEventDisableTiming);
        cudaEventCreateWithFlags(&g_evFork, cudaEventDisableTiming);
        cudaEventCreateWithFlags(&g_evJoin, cudaEventDisableTiming);
    }

    // ---- legal capture fork at t=0: g_sB joins the capture via evStart ----
    cudaEventRecord(g_evStart, 0);
    cudaStreamWaitEvent(g_sB, g_evStart, 0);

    // DFT weight tables on g_sB (input-independent; overlaps prologue + GEMM1)
    init_wdft_kernel<<<(MR * D_ + T_ * KI + 255) / 256, 256, 0, g_sB>>>();

    // ---- prologue on stream 0 ----
    init_div_kernel<<<1, 512>>>();
    init_pe_kernel<<<(T_ * D_ + 255) / 256, 256>>>();
    pad_kernel<<<((B_ * T_ + D_) * KPAD + 255) / 256, 256>>>(x, W_emb);

    // ex = x * W_emb^T + b_emb + PE      (padded K=272)
    sgemm2_kernel<EPI_PE, 0><<<dim3(D_ / 64, B_ * T_ / 64), 128>>>(
        p_xpad, KPAD, 0, p_wpad, KPAD, 0, p_ex, D_, 0, D_, KPAD,
        b_emb, nullptr, nullptr, nullptr, nullptr, nullptr, nullptr);

    // ---- fork: path B (frequency) continues on g_sB after ex is ready ----
    cudaEventRecord(g_evFork, 0);
    cudaStreamWaitEvent(g_sB, g_evFork, 0);
    {
        // cf[b] = Wdft[640,512] @ ex[b][512,512]   (re rows 0..256, im rows 320..576)
        sgemm2_kernel<EPI_NONE, 1><<<dim3(D_ / 64, MR / 64, B_), 128, 0, g_sB>>>(
            p_wdft, D_, 0, p_ex, D_, (long)T_ * D_, p_cf, D_, (long)MR * D_, D_, D_,
            nullptr, nullptr, nullptr, nullptr, nullptr, nullptr, nullptr);
        mag_kernel<<<B_ * F_, 512, 0, g_sB>>>();
        topk_kernel<<<B_, 512, 0, g_sB>>>(p_mag, F_, K_TOP, p_fidx, p_fmask, out_fidx);
        tm_kernel<<<B_, 512, 0, g_sB>>>();
        buildfin_kernel<<<(B_ * KI * D_ + 255) / 256, 256, 0, g_sB>>>(f_tok_re, f_tok_im);
        // mtd[b] = Widft[512,544] @ fin[b][544,512]
        sgemm2_kernel<EPI_NONE, 1><<<dim3(D_ / 64, T_ / 64, B_), 128, 0, g_sB>>>(
            p_widft, KI, 0, p_fin, D_, (long)KI * D_, p_mtd, D_, (long)T_ * D_, D_, KI,
            nullptr, nullptr, nullptr, nullptr, nullptr, nullptr, nullptr);
        // out_f = tmsel(mtd @ W_emb)   (fused mx + outf)
        sgemm2_kernel<EPI_TMSEL, 1><<<dim3((C_ + 63) / 64, B_ * T_ / 64), 128, 0, g_sB>>>(
            p_mtd, D_, 0, p_wpad, KPAD, 0, out_f, C_, 0, C_, D_,
            nullptr, p_tm, nullptr, fW1, fb1, fW2, fb2);
        cudaEventRecord(g_evJoin, g_sB);
    }

    // ---- path A (temporal) on stream 0 ----
    score_kernel<<<B_ * T_, 256>>>();
    topk_kernel<<<B_, 512>>>(p_score, T_, K_TOP, p_tidx, p_tmask, out_tidx);
    // h = gelu(ex * tW1^T + tb1)
    sgemm2_kernel<EPI_GELU, 0><<<dim3(D_ / 64, B_ * T_ / 64), 128>>>(
        p_ex, D_, 0, tW1, D_, 0, p_h, D_, 0, D_, D_,
        tb1, nullptr, nullptr, nullptr, nullptr, nullptr, nullptr);
    // out_t = tmask ? t_token : sigmoid(h * tW2^T + tb2)
    sgemm2_kernel<EPI_SIGMASK, 0><<<dim3(D_ / 64, B_ * T_ / 64), 128>>>(
        p_h, D_, 0, tW2, D_, 0, out_t, D_, 0, D_, D_,
        tb2, p_tmask, t_token, nullptr, nullptr, nullptr, nullptr);

    // ---- join ----
    cudaStreamWaitEvent(0, g_evJoin, 0);
}

// round 6
// speedup vs baseline: 2.4296x; 1.2332x over previous
#include <cuda_runtime.h>
#include <math.h>

#define B_ 2
#define T_ 512
#define C_ 263
#define D_ 512
#define F_ 257          // T/2 + 1
#define K_TOP 51        // int(512 * 0.1)
#define WIN_ 24
#define KPAD 272        // 263 padded to multiple of 16 (zero-filled)

// packed spectrum: row f in [0,256] = re_f ; row 256+f for f in [1,255] = im_f
#define MR 512          // rfft GEMM M (packed, no waste)
#define KI 512          // irfft GEMM K (packed)

// ---------------- scratch (static device memory; no allocation) ----------------
__device__ float g_ex [B_*T_*D_];
__device__ float g_h  [B_*T_*D_];
__device__ float g_mtd[B_*T_*D_];
__device__ float g_cf [B_*MR*D_];       // packed spectrum per b
__device__ float g_fin[B_*KI*D_];       // masked packed spectrum per b
__device__ float g_score[B_*T_];
__device__ float g_mag  [B_*F_];
__device__ int   g_tidx[B_*K_TOP];
__device__ int   g_fidx[B_*K_TOP];
__device__ unsigned char g_tmask[B_*T_];
__device__ unsigned char g_fmask[B_*F_];
__device__ unsigned char g_tm   [B_*T_];
__device__ float g_costab[512];
__device__ float g_sintab[512];
__device__ float g_pe[T_*D_];
__device__ double g_div[256];           // PE divisors (fp64)
__device__ float g_xpad[B_*T_*KPAD + 64];   // x zero-padded to K=272
__device__ float g_wpad[D_*KPAD + 64];      // W_emb zero-padded to 272 cols
__device__ float g_wdft [MR*T_];        // rfft weights  [512][512]
__device__ float g_widft[T_*KI];        // irfft weights [512][512]

// ---------------- stream/event (created in static ctor, pre-checkpoint) --------
static cudaStream_t g_sB = nullptr;
static cudaEvent_t g_evStart = nullptr, g_evFork = nullptr, g_evJoin = nullptr;
namespace {
struct StreamInit {
    StreamInit() {
        cudaStreamCreateWithFlags(&g_sB, cudaStreamNonBlocking);
        cudaEventCreateWithFlags(&g_evStart, cudaEventDisableTiming);
        cudaEventCreateWithFlags(&g_evFork, cudaEventDisableTiming);
        cudaEventCreateWithFlags(&g_evJoin, cudaEventDisableTiming);
    }
};
StreamInit g_streamInit;
}

// ---------------- table init ----------------------------------------------------
__global__ void init_div_kernel() {
    int i = threadIdx.x;                 // 512 threads
    if (i < 256) {
        g_div[i] = exp(-(double)(2 * i) * (9.210340371976184 / 512.0));
    }
    if (i < 512) {
        float s, c;
        sincospif((float)i / 256.0f, &s, &c);   // 2*pi*i/512
        g_costab[i] = c; g_sintab[i] = s;
    }
}

__global__ void init_pe_kernel() {
    int i = blockIdx.x * blockDim.x + threadIdx.x;
    if (i >= T_ * D_) return;
    int t = i / D_, d = i % D_;
    double arg = (double)t * g_div[d >> 1];
    const double PI2 = 6.283185307179586476925286766559;
    double q = rint(arg * (1.0 / PI2));
    float rf = (float)(arg - q * PI2);
    g_pe[i] = (d & 1) ? cosf(rf) : sinf(rf);
}

// DFT weight tables (input-independent; identical twiddle values)
__global__ void init_wdft_kernel() {
    int i = blockIdx.x * blockDim.x + threadIdx.x;
    const int n1 = MR * T_;
    if (i < n1) {
        int r = i >> 9, t = i & 511;
        float s, c;
        if (r <= 256) {                 // cos row, f = r
            sincospif((float)((r * t) & 511) / 256.0f, &s, &c);
            g_wdft[i] = c;
        } else {                        // -sin row, f = r-256 (1..255)
            sincospif((float)(((r - 256) * t) & 511) / 256.0f, &s, &c);
            g_wdft[i] = -s;
        }
    } else {
        int j = i - n1;
        if (j < T_ * KI) {
            int t = j >> 9, c = j & 511;
            float s, cc;
            if (c <= 256) {             // re weight, f = c
                float w = (c == 0 || c == 256) ? (1.f / 512.f) : (2.f / 512.f);
                sincospif((float)((c * t) & 511) / 256.0f, &s, &cc);
                g_widft[j] = w * cc;
            } else {                    // im weight, f = c-256 (1..255)
                int f = c - 256;
                sincospif((float)((f * t) & 511) / 256.0f, &s, &cc);
                g_widft[j] = -(2.f / 512.f) * s;
            }
        }
    }
}

// pad x -> [B*T][272] and W_emb -> [D][272] in one kernel
__global__ void pad_kernel(const float* __restrict__ x, const float* __restrict__ w) {
    int i = blockIdx.x * blockDim.x + threadIdx.x;
    const int n1 = B_ * T_ * KPAD;
    if (i < n1) {
        int r = i / KPAD, c = i % KPAD;
        g_xpad[i] = (c < C_) ? x[r * C_ + c] : 0.f;
    } else {
        int j = i - n1;
        if (j < D_ * KPAD) {
            int r = j / KPAD, c = j % KPAD;
            g_wpad[j] = (c < C_) ? w[r * C_ + c] : 0.f;
        }
    }
}

// ---------------- SGEMM v3: 64x64x16 tile, 256 threads, 4x4/thread, float4 -----
#define EPI_NONE    0
#define EPI_PE      2
#define EPI_GELU    3
#define EPI_SIGMASK 4
#define EPI_TMSEL   5

// C[M, N] = A[M, K](lda) * B(^T).  K mult of 16, M mult of 64 (per batch).
// BKN=0: B is [N][K] row-major (ldb = row stride)  -> A*B^T
// BKN=1: B is [K][ldb] row-major, logical [K][N]   -> A*B  (cols >= ldb read as 0)
// blockIdx.z batches: A += z*sA, B += z*sB, C += z*sC.
template <int EPI, int BKN>
__global__ void __launch_bounds__(256) sgemm3_kernel(
        const float* __restrict__ A, int lda, long sA,
        const float* __restrict__ B, int ldb, long sB,
        float* __restrict__ Cm, int ldc, long sC, int N, int K,
        const float* __restrict__ bias,
        const unsigned char* __restrict__ mask,
        const float* __restrict__ token,
        const float* __restrict__ e1, const float* __restrict__ e2,
        const float* __restrict__ e3, const float* __restrict__ e4)
{
    A += (long)blockIdx.z * sA;
    B += (long)blockIdx.z * sB;
    Cm += (long)blockIdx.z * sC;
    __shared__ float As[16][64];
    __shared__ float Bs[16][64];
    int tid = threadIdx.x;            // 256
    int bm = blockIdx.y * 64;
    int bn = blockIdx.x * 64;
    int tx = (tid & 15) * 4;          // n offset 0..60
    int ty = (tid >> 4) * 4;          // m offset 0..60
    int lrow = tid >> 2, lkq = (tid & 3) * 4;   // A / B^T tile load
    float acc[4][4] = {};

    for (int k0 = 0; k0 < K; k0 += 16) {
        {
            float4 v = *(const float4*)&A[(size_t)(bm + lrow) * lda + k0 + lkq];
            As[lkq + 0][lrow] = v.x; As[lkq + 1][lrow] = v.y;
            As[lkq + 2][lrow] = v.z; As[lkq + 3][lrow] = v.w;
        }
        if (BKN) {
            int kk = tid >> 4, nn = (tid & 15) * 4;
            float4 v = make_float4(0.f, 0.f, 0.f, 0.f);
            if (bn + nn < ldb)
                v = *(const float4*)&B[(size_t)(k0 + kk) * ldb + bn + nn];
            *(float4*)&Bs[kk][nn] = v;
        } else {
            float4 v = *(const float4*)&B[(size_t)(bn + lrow) * ldb + k0 + lkq];
            Bs[lkq + 0][lrow] = v.x; Bs[lkq + 1][lrow] = v.y;
            Bs[lkq + 2][lrow] = v.z; Bs[lkq + 3][lrow] = v.w;
        }
        __syncthreads();
        #pragma unroll
        for (int kk = 0; kk < 16; kk++) {
            float4 a = *(const float4*)&As[kk][ty];
            float4 b = *(const float4*)&Bs[kk][tx];
            float am[4] = {a.x, a.y, a.z, a.w};
            float bv[4] = {b.x, b.y, b.z, b.w};
            #pragma unroll
            for (int i = 0; i < 4; i++)
                #pragma unroll
                for (int j = 0; j < 4; j++)
                    acc[i][j] = fmaf(am[i], bv[j], acc[i][j]);
        }
        __syncthreads();
    }

    const bool vec = ((N & 3) == 0);
    #pragma unroll
    for (int i = 0; i < 4; i++) {
        int row = bm + ty + i;
        float v4[4];
        #pragma unroll
        for (int j = 0; j < 4; j++) {
            int col = bn + tx + j;
            float v = acc[i][j];
            if (EPI == EPI_PE) {
                v += bias[col];
                v += g_pe[(row & (T_ - 1)) * D_ + col];
            } else if (EPI == EPI_GELU) {
                v += bias[col];
                v = 0.5f * v * (1.f + erff(v * 0.70710678118654752f));
            } else if (EPI == EPI_SIGMASK) {
                v += bias[col];
                v = 1.f / (1.f + expf(-v));
                if (mask[row]) v = token[col];
            } else if (EPI == EPI_TMSEL) {
                // out_f: keep mx where tm, else per-element scalar MLP (usually dead)
                if (!mask[row]) {
                    float m = v, a = 0.f;
                    for (int dd = 0; dd < D_; dd++) {
                        float u = fmaf(m, e1[dd], e2[dd]);
                        float g = 0.5f * u * (1.f + erff(u * 0.70710678118654752f));
                        a = fmaf(g, e3[dd], a);
                    }
                    v = 1.f / (1.f + expf(-(a + e4[0])));
                }
            }
            v4[j] = v;
        }
        if (vec) {
            *(float4*)&Cm[(size_t)row * ldc + bn + tx] =
                make_float4(v4[0], v4[1], v4[2], v4[3]);
        } else {
            #pragma unroll
            for (int j = 0; j < 4; j++) {
                int col = bn + tx + j;
                if (col < N) Cm[(size_t)row * ldc + col] = v4[j];
            }
        }
    }
}

// ---------------- windowed-variance score: one block per (b,t) -----------------
__global__ void score_kernel() {
    int bt = blockIdx.x;
    int b = bt >> 9, t = bt & 511;
    int tid = threadIdx.x;            // 256
    int t0 = t - (WIN_ - 1); if (t0 < 0) t0 = 0;
    float denom = (float)((t + 1 < WIN_) ? (t + 1) : WIN_);
    float num = 0.f, den = 0.f;
    for (int d = tid; d < D_; d += 256) {
        float s1 = 0.f, s2 = 0.f;
        const float* p = &g_ex[((size_t)b * T_ + t0) * D_ + d];
        for (int tt = t0; tt <= t; tt++) {
            float v = *p; p += D_;
            s1 += v;
            s2 = fmaf(v, v, s2);
        }
        float m1 = s1 / denom;
        num += s2 / denom - m1 * m1;
        den += m1;
    }
    __shared__ float sn[256], sd[256];
    sn[tid] = num; sd[tid] = den; __syncthreads();
    for (int s = 128; s > 0; s >>= 1) {
        if (tid < s) { sn[tid] += sn[tid + s]; sd[tid] += sd[tid + s]; }
        __syncthreads();
    }
    if (tid == 0) g_score[bt] = sn[0] / (sd[0] + 1e-6f);
}

// ---------------- top-k via rank selection (lax.top_k stable-desc semantics) ---
__global__ void topk_kernel(const float* __restrict__ vals, int n, int k,
                            int* __restrict__ idx_out,
                            unsigned char* __restrict__ mask_out,
                            float* __restrict__ outf)
{
    int b = blockIdx.x;
    int tid = threadIdx.x;            // 512
    __shared__ float v[512];
    for (int i = tid; i < n; i += blockDim.x) v[i] = vals[b * n + i];
    if (tid < n) mask_out[b * n + tid] = 0;
    __syncthreads();
    if (tid < n) {
        float x = v[tid];
        int rank = 0;
        for (int j = 0; j < n; j++) {
            float y = v[j];
            rank += (y > x) || (y == x && j < tid);
        }
        if (rank < k) {
            idx_out[b * k + rank] = tid;
            outf[b * k + rank] = (float)tid;
            mask_out[b * n + tid] = 1;
        }
    }
}

// ---------------- magnitude mean over d: one block per (b,f) -------------------
__global__ void mag_kernel() {
    int bf = blockIdx.x;
    int b = bf / F_, f = bf % F_;
    int d = threadIdx.x;              // 512
    float cr = g_cf[((size_t)b * MR + f) * D_ + d];
    float ci = (f == 0 || f == 256) ? 0.f
             : g_cf[((size_t)b * MR + 256 + f) * D_ + d];
    float m = sqrtf(cr * cr + ci * ci);
    __shared__ float red[512];
    red[d] = m; __syncthreads();
    for (int s = 256; s > 0; s >>= 1) {
        if (d < s) red[d] += red[d + s];
        __syncthreads();
    }
    if (d == 0) g_mag[bf] = red[0] * (1.f / 512.f);
}

// ---------------- time-domain mask tm = irfft(fmask) != 0 ----------------------
__global__ void tm_kernel() {
    int b = blockIdx.x;
    int t = threadIdx.x;              // 512
    const unsigned char* fm = &g_fmask[b * F_];
    float y = fm[0] ? 1.f : 0.f;
    for (int f = 1; f < 256; f++)
        if (fm[f]) y += 2.f * g_costab[(f * t) & 511];
    if (fm[256]) y += (t & 1) ? -1.f : 1.f;
    g_tm[b * T_ + t] = (y != 0.f) ? 1 : 0;
}

// ---------------- build masked packed spectrum for irfft GEMM ------------------
__global__ void buildfin_kernel(const float* __restrict__ f_tok_re,
                                const float* __restrict__ f_tok_im) {
    int i = blockIdx.x * blockDim.x + threadIdx.x;
    if (i >= B_ * KI * D_) return;
    int b = i / (KI * D_);
    int rem = i - b * KI * D_;
    int r = rem >> 9, d = rem & 511;
    int f = (r <= 256) ? r : (r - 256);
    float v;
    if (g_fmask[b * F_ + f]) v = (r <= 256) ? f_tok_re[d] : f_tok_im[d];
    else                     v = g_cf[(size_t)b * MR * D_ + rem];
    g_fin[i] = v;
}

// ---------------- launch ----------------
extern "C" void kernel_launch(void* const* d_in, const int* in_sizes, int n_in,
                              void* d_out, int out_size) {
    const float* x        = (const float*)d_in[0];
    const float* W_emb    = (const float*)d_in[1];
    const float* b_emb    = (const float*)d_in[2];
    const float* t_token  = (const float*)d_in[3];
    const float* tW1      = (const float*)d_in[4];
    const float* tb1      = (const float*)d_in[5];
    const float* tW2      = (const float*)d_in[6];
    const float* tb2      = (const float*)d_in[7];
    const float* f_tok_re = (const float*)d_in[8];
    const float* f_tok_im = (const float*)d_in[9];
    const float* fW1      = (const float*)d_in[10];
    const float* fb1      = (const float*)d_in[11];
    const float* fW2      = (const float*)d_in[12];
    const float* fb2      = (const float*)d_in[13];
    float* out = (float*)d_out;

    // output packing: out_t [B,T,D] | tidx [B,51] | out_f [B,T,C] | fidx [B,51]
    float* out_t    = out;
    float* out_tidx = out + (size_t)B_ * T_ * D_;
    float* out_f    = out_tidx + B_ * K_TOP;
    float* out_fidx = out_f + (size_t)B_ * T_ * C_;

    float *p_ex, *p_h, *p_mtd, *p_score, *p_mag, *p_xpad, *p_wpad;
    float *p_wdft, *p_widft, *p_cf, *p_fin;
    int *p_tidx, *p_fidx;
    unsigned char *p_tmask, *p_fmask, *p_tm;
    cudaGetSymbolAddress((void**)&p_ex,    g_ex);
    cudaGetSymbolAddress((void**)&p_h,     g_h);
    cudaGetSymbolAddress((void**)&p_mtd,   g_mtd);
    cudaGetSymbolAddress((void**)&p_score, g_score);
    cudaGetSymbolAddress((void**)&p_mag,   g_mag);
    cudaGetSymbolAddress((void**)&p_xpad,  g_xpad);
    cudaGetSymbolAddress((void**)&p_wpad,  g_wpad);
    cudaGetSymbolAddress((void**)&p_wdft,  g_wdft);
    cudaGetSymbolAddress((void**)&p_widft, g_widft);
    cudaGetSymbolAddress((void**)&p_cf,    g_cf);
    cudaGetSymbolAddress((void**)&p_fin,   g_fin);
    cudaGetSymbolAddress((void**)&p_tidx,  g_tidx);
    cudaGetSymbolAddress((void**)&p_fidx,  g_fidx);
    cudaGetSymbolAddress((void**)&p_tmask, g_tmask);
    cudaGetSymbolAddress((void**)&p_fmask, g_fmask);
    cudaGetSymbolAddress((void**)&p_tm,    g_tm);

    if (!g_sB) {
        cudaStreamCreateWithFlags(&g_sB, cudaStreamNonBlocking);
        cudaEventCreateWithFlags(&g_evStart, cudaEventDisableTiming);
        cudaEventCreateWithFlags(&g_evFork, cudaEventDisableTiming);
        cudaEventCreateWithFlags(&g_evJoin, cudaEventDisableTiming);
    }

    // ---- legal capture fork at t=0: g_sB joins the capture via evStart ----
    cudaEventRecord(g_evStart, 0);
    cudaStreamWaitEvent(g_sB, g_evStart, 0);

    // DFT weight tables on g_sB (input-independent; overlaps prologue + GEMM1)
    init_wdft_kernel<<<(MR * T_ + T_ * KI + 255) / 256, 256, 0, g_sB>>>();

    // ---- prologue on stream 0 ----
    init_div_kernel<<<1, 512>>>();
    init_pe_kernel<<<(T_ * D_ + 255) / 256, 256>>>();
    pad_kernel<<<((B_ * T_ + D_) * KPAD + 255) / 256, 256>>>(x, W_emb);

    // ex = x * W_emb^T + b_emb + PE      (padded K=272)
    sgemm3_kernel<EPI_PE, 0><<<dim3(D_ / 64, B_ * T_ / 64), 256>>>(
        p_xpad, KPAD, 0, p_wpad, KPAD, 0, p_ex, D_, 0, D_, KPAD,
        b_emb, nullptr, nullptr, nullptr, nullptr, nullptr, nullptr);

    // ---- fork: path B (frequency) continues on g_sB after ex is ready ----
    cudaEventRecord(g_evFork, 0);
    cudaStreamWaitEvent(g_sB, g_evFork, 0);
    {
        // cf[b] = Wdft[512,512] @ ex[b][512,512]   (packed re/im rows)
        sgemm3_kernel<EPI_NONE, 1><<<dim3(D_ / 64, MR / 64, B_), 256, 0, g_sB>>>(
            p_wdft, T_, 0, p_ex, D_, (long)T_ * D_, p_cf, D_, (long)MR * D_, D_, T_,
            nullptr, nullptr, nullptr, nullptr, nullptr, nullptr, nullptr);
        mag_kernel<<<B_ * F_, 512, 0, g_sB>>>();
        topk_kernel<<<B_, 512, 0, g_sB>>>(p_mag, F_, K_TOP, p_fidx, p_fmask, out_fidx);
        tm_kernel<<<B_, 512, 0, g_sB>>>();
        buildfin_kernel<<<(B_ * KI * D_ + 255) / 256, 256, 0, g_sB>>>(f_tok_re, f_tok_im);
        // mtd[b] = Widft[512,512] @ fin[b][512,512]
        sgemm3_kernel<EPI_NONE, 1><<<dim3(D_ / 64, T_ / 64, B_), 256, 0, g_sB>>>(
            p_widft, KI, 0, p_fin, D_, (long)KI * D_, p_mtd, D_, (long)T_ * D_, D_, KI,
            nullptr, nullptr, nullptr, nullptr, nullptr, nullptr, nullptr);
        // out_f = tmsel(mtd @ W_emb)   (fused mx + outf)
        sgemm3_kernel<EPI_TMSEL, 1><<<dim3((C_ + 63) / 64, B_ * T_ / 64), 256, 0, g_sB>>>(
            p_mtd, D_, 0, p_wpad, KPAD, 0, out_f, C_, 0, C_, D_,
            nullptr, p_tm, nullptr, fW1, fb1, fW2, fb2);
        cudaEventRecord(g_evJoin, g_sB);
    }

    // ---- path A (temporal) on stream 0 ----
    score_kernel<<<B_ * T_, 256>>>();
    topk_kernel<<<B_, 512>>>(p_score, T_, K_TOP, p_tidx, p_tmask, out_tidx);
    // h = gelu(ex * tW1^T + tb1)
    sgemm3_kernel<EPI_GELU, 0><<<dim3(D_ / 64, B_ * T_ / 64), 256>>>(
        p_ex, D_, 0, tW1, D_, 0, p_h, D_, 0, D_, D_,
        tb1, nullptr, nullptr, nullptr, nullptr, nullptr, nullptr);
    // out_t = tmask ? t_token : sigmoid(h * tW2^T + tb2)
    sgemm3_kernel<EPI_SIGMASK, 0><<<dim3(D_ / 64, B_ * T_ / 64), 256>>>(
        p_h, D_, 0, tW2, D_, 0, out_t, D_, 0, D_, D_,
        tb2, p_tmask, t_token, nullptr, nullptr, nullptr, nullptr);

    // ---- join ----
    cudaStreamWaitEvent(0, g_evJoin, 0);
}